// round 1
// baseline (speedup 1.0000x reference)
#include <cuda_runtime.h>
#include <cuda_bf16.h>
#include <math.h>

#define B_    2
#define N_    1024
#define DIM_  512
#define NH_   8
#define HD_   64
#define WIN_  64
#define M_    (B_ * N_)      // 2048
#define DFF_  (4 * DIM_)     // 2048
#define EPSV  1e-7f

// ------------------------ scratch (device globals; no allocation) ------------
__device__ float g_xn  [M_ * DIM_];
__device__ float g_q   [M_ * DIM_];
__device__ float g_k   [M_ * DIM_];
__device__ float g_v   [M_ * DIM_];
__device__ float g_qh  [B_ * NH_ * N_ * HD_];
__device__ float g_kh  [B_ * NH_ * N_ * HD_];
__device__ float g_vt  [B_ * NH_ * N_ * HD_];
__device__ float g_attn[M_ * DIM_];
__device__ float g_xout[M_ * DIM_];
__device__ float g_h   [M_ * DIM_];
__device__ float g_mid [M_ * DFF_];

// ------------------------ helpers -------------------------------------------
__device__ __forceinline__ float warpsum(float v) {
#pragma unroll
    for (int o = 16; o > 0; o >>= 1) v += __shfl_xor_sync(0xffffffffu, v, o);
    return v;
}
__device__ __forceinline__ float warpmax(float v) {
#pragma unroll
    for (int o = 16; o > 0; o >>= 1) v = fmaxf(v, __shfl_xor_sync(0xffffffffu, v, o));
    return v;
}

// ------------------------ layernorm -----------------------------------------
// one block (128 threads) per row of 512
__global__ void ln_kernel(const float* __restrict__ x, const float* __restrict__ s,
                          const float* __restrict__ bsh, float* __restrict__ out) {
    int row = blockIdx.x;
    const float* xr = x + (size_t)row * DIM_;
    float v[4];
    float sum = 0.f, sq = 0.f;
#pragma unroll
    for (int i = 0; i < 4; i++) {
        v[i] = xr[threadIdx.x + i * 128];
        sum += v[i];
        sq  += v[i] * v[i];
    }
    __shared__ float red0[4], red1[4];
    sum = warpsum(sum); sq = warpsum(sq);
    int warp = threadIdx.x >> 5, lane = threadIdx.x & 31;
    if (lane == 0) { red0[warp] = sum; red1[warp] = sq; }
    __syncthreads();
    sum = red0[0] + red0[1] + red0[2] + red0[3];
    sq  = red1[0] + red1[1] + red1[2] + red1[3];
    float mean = sum * (1.0f / DIM_);
    float var  = sq * (1.0f / DIM_) - mean * mean;
    float inv  = rsqrtf(var + 1e-6f);
    float* orow = out + (size_t)row * DIM_;
#pragma unroll
    for (int i = 0; i < 4; i++) {
        int d = threadIdx.x + i * 128;
        orow[d] = (v[i] - mean) * inv * s[d] + bsh[d];
    }
}

// ------------------------ SGEMM: C[M,N] = A[M,K]@B[K,N] + epilogue -----------
// BM=128 BN=64 BK=16, 256 threads, 8x4 per thread
#define BM 128
#define BN 64
#define BK 16
// EPI: 0 = +bias, 1 = +bias+residual, 2 = gelu(+bias)
template <int EPI>
__global__ __launch_bounds__(256) void gemm_kernel(
    const float* __restrict__ A, const float* __restrict__ Bw,
    const float* __restrict__ bias, const float* __restrict__ res,
    float* __restrict__ C, int Md, int Nd, int Kd) {
    __shared__ float As[BK][BM];
    __shared__ float Bs[BK][BN];
    int m0 = blockIdx.y * BM;
    int n0 = blockIdx.x * BN;
    int tid = threadIdx.x;
    int rt = tid >> 4;   // 0..15
    int ct = tid & 15;   // 0..15

    float acc[8][4];
#pragma unroll
    for (int i = 0; i < 8; i++)
#pragma unroll
        for (int j = 0; j < 4; j++) acc[i][j] = 0.f;

    for (int k0 = 0; k0 < Kd; k0 += BK) {
        // A tile: 128x16 = 512 float4; 2 per thread, stored transposed
#pragma unroll
        for (int u = 0; u < 2; u++) {
            int f = tid + u * 256;
            int arow = f >> 2;
            int akc  = (f & 3) * 4;
            float4 av = *(const float4*)(A + (size_t)(m0 + arow) * Kd + k0 + akc);
            As[akc + 0][arow] = av.x;
            As[akc + 1][arow] = av.y;
            As[akc + 2][arow] = av.z;
            As[akc + 3][arow] = av.w;
        }
        // B tile: 16x64 = 256 float4; 1 per thread
        {
            int brow = tid >> 4;
            int bc4  = (tid & 15) * 4;
            *(float4*)&Bs[brow][bc4] =
                *(const float4*)(Bw + (size_t)(k0 + brow) * Nd + n0 + bc4);
        }
        __syncthreads();
#pragma unroll
        for (int k = 0; k < BK; k++) {
            float af[8], bf[4];
            *(float4*)&af[0] = *(const float4*)&As[k][rt * 8];
            *(float4*)&af[4] = *(const float4*)&As[k][rt * 8 + 4];
            *(float4*)&bf[0] = *(const float4*)&Bs[k][ct * 4];
#pragma unroll
            for (int i = 0; i < 8; i++)
#pragma unroll
                for (int j = 0; j < 4; j++) acc[i][j] = fmaf(af[i], bf[j], acc[i][j]);
        }
        __syncthreads();
    }
#pragma unroll
    for (int i = 0; i < 8; i++) {
        int m = m0 + rt * 8 + i;
#pragma unroll
        for (int j = 0; j < 4; j++) {
            int n = n0 + ct * 4 + j;
            float v = acc[i][j] + bias[n];
            if (EPI == 1) v += res[(size_t)m * Nd + n];
            if (EPI == 2) {
                float t = v;
                v = 0.5f * t * (1.f + tanhf(0.7978845608028654f * (t + 0.044715f * t * t * t)));
            }
            C[(size_t)m * Nd + n] = v;
        }
    }
}

// ------------------------ prep: hash + rope + expmap0 + transpose ------------
// grid 2048 (= b*N+n), 256 threads: warp = head, lane handles dims (l, l+32)
__global__ void prep_kernel(const float* __restrict__ qb, const float* __restrict__ kb,
                            const float* __restrict__ vb, const float* __restrict__ cos_t,
                            const float* __restrict__ sin_t, const float* __restrict__ c_arr,
                            const float* __restrict__ hash_off,
                            float* __restrict__ qh, float* __restrict__ kh,
                            float* __restrict__ vt) {
    int bn = blockIdx.x;
    int b = bn / N_, n = bn % N_;
    int h = threadIdx.x >> 5, lane = threadIdx.x & 31;
    const float LOG9 = 2.1972245773362196f;  // log(1 + HASH_WIN)
    float cs = cos_t[n * 32 + lane];
    float sn = sin_t[n * 32 + lane];
    float cb = c_arr[b];
    float sqrt_c = fmaxf(sqrtf(cb), EPSV);
    size_t in_off  = (size_t)bn * DIM_ + h * HD_;
    size_t out_off = (((size_t)(b * NH_ + h)) * N_ + n) * HD_;

    // ---- q: +hash, rope, expmap0
    {
        float v0 = qb[in_off + lane]      + hash_off[h * HD_ + lane]      * LOG9;
        float v1 = qb[in_off + lane + 32] + hash_off[h * HD_ + lane + 32] * LOG9;
        float r0 = v0 * cs - v1 * sn;
        float r1 = v0 * sn + v1 * cs;
        float nrm = sqrtf(warpsum(r0 * r0 + r1 * r1));
        float o0 = 0.f, o1 = 0.f;
        if (nrm >= EPSV) {
            float safe = fmaxf(nrm, EPSV);
            float mag  = tanhf(sqrt_c * safe) / sqrt_c;
            float sc   = mag / safe;
            o0 = sc * r0; o1 = sc * r1;
        }
        qh[out_off + lane] = o0; qh[out_off + lane + 32] = o1;
    }
    // ---- k: rope, expmap0
    {
        float v0 = kb[in_off + lane];
        float v1 = kb[in_off + lane + 32];
        float r0 = v0 * cs - v1 * sn;
        float r1 = v0 * sn + v1 * cs;
        float nrm = sqrtf(warpsum(r0 * r0 + r1 * r1));
        float o0 = 0.f, o1 = 0.f;
        if (nrm >= EPSV) {
            float safe = fmaxf(nrm, EPSV);
            float mag  = tanhf(sqrt_c * safe) / sqrt_c;
            float sc   = mag / safe;
            o0 = sc * r0; o1 = sc * r1;
        }
        kh[out_off + lane] = o0; kh[out_off + lane + 32] = o1;
    }
    // ---- v: transpose only
    vt[out_off + lane]      = vb[in_off + lane];
    vt[out_off + lane + 32] = vb[in_off + lane + 32];
}

// ------------------------ windowed Poincaré attention ------------------------
// grid (N/64, B*NH), 256 threads (8 warps x 8 queries each)
// two-phase smem: phase 1 = K tile -> scores/softmax weights (regs),
//                 phase 2 = V tile (reuses smem) -> AV
#define QT 64
#define KROWS (QT + WIN_ - 1)  // 127
__global__ __launch_bounds__(256) void attn_kernel(
    const float* __restrict__ qh, const float* __restrict__ kh,
    const float* __restrict__ vt, const float* __restrict__ c_arr,
    const float* __restrict__ geo, float* __restrict__ attn_out) {
    __shared__ float Ks[KROWS][HD_];
    __shared__ float y2s[KROWS];
    int bh = blockIdx.y;
    int b = bh / NH_, h = bh % NH_;
    int n0 = blockIdx.x * QT;
    int warp = threadIdx.x >> 5, lane = threadIdx.x & 31;

    const float* Kbase = kh + (size_t)bh * N_ * HD_;
    // load K tile (rows = keys n0-63 .. n0+63), zero-pad left boundary
    for (int f = threadIdx.x; f < KROWS * 16; f += 256) {
        int row = f >> 4, c4 = (f & 15) * 4;
        int gn = n0 - (WIN_ - 1) + row;
        float4 val = (gn >= 0) ? *(const float4*)(Kbase + (size_t)gn * HD_ + c4)
                               : make_float4(0.f, 0.f, 0.f, 0.f);
        *(float4*)&Ks[row][c4] = val;
    }
    __syncthreads();
    // y2 per key row (warp per row, conflict-free)
    for (int row = warp; row < KROWS; row += 8) {
        float a = Ks[row][lane], c2 = Ks[row][lane + 32];
        float s = warpsum(a * a + c2 * c2);
        if (lane == 0) y2s[row] = s;
    }
    __syncthreads();

    float cb = c_arr[b];
    float sqrt_c = fmaxf(sqrtf(cb), EPSV);
    float inv_sqrt_c = 1.0f / sqrt_c;
    float gs = geo[h];
    float w0a[8], w1a[8];

    for (int iq = 0; iq < 8; iq++) {
        int nl = warp * 8 + iq;
        int n = n0 + nl;
        const float* qrow = qh + ((size_t)bh * N_ + n) * HD_;
        float q0 = qrow[lane], q1 = qrow[lane + 32];
        float x2 = warpsum(q0 * q0 + q1 * q1);
        float Bc = 1.f - cb * x2;
        float s0 = -1e30f, s1 = -1e30f;
#pragma unroll 4
        for (int k = 0; k < WIN_; k++) {
            int row = nl + k;
            float xy = warpsum(q0 * Ks[row][lane] + q1 * Ks[row][lane + 32]);
            float y2 = y2s[row];
            float A   = 1.f - 2.f * cb * xy + cb * y2;
            float dn2 = A * A * x2 + Bc * Bc * y2 - 2.f * A * Bc * xy;
            float den = fmaxf(1.f - 2.f * cb * xy + cb * cb * x2 * y2, EPSV);
            float dn  = sqrtf(fmaxf(dn2, 0.f)) / den;
            float arg = fminf(sqrt_c * fmaxf(dn, EPSV), 1.f - EPSV);
            float dist = 2.f * atanhf(arg) * inv_sqrt_c;
            float sc = -gs * dist;
            if (k == lane)      s0 = sc;
            if (k == lane + 32) s1 = sc;
        }
        float m  = warpmax(fmaxf(s0, s1));
        float e0 = __expf(s0 - m), e1 = __expf(s1 - m);
        float sum = warpsum(e0 + e1);
        float inv = 1.0f / sum;
        w0a[iq] = e0 * inv; w1a[iq] = e1 * inv;
    }
    __syncthreads();

    // phase 2: V tile into the same smem
    const float* Vbase = vt + (size_t)bh * N_ * HD_;
    for (int f = threadIdx.x; f < KROWS * 16; f += 256) {
        int row = f >> 4, c4 = (f & 15) * 4;
        int gn = n0 - (WIN_ - 1) + row;
        float4 val = (gn >= 0) ? *(const float4*)(Vbase + (size_t)gn * HD_ + c4)
                               : make_float4(0.f, 0.f, 0.f, 0.f);
        *(float4*)&Ks[row][c4] = val;
    }
    __syncthreads();

    for (int iq = 0; iq < 8; iq++) {
        int nl = warp * 8 + iq;
        int n = n0 + nl;
        float w0 = w0a[iq], w1 = w1a[iq];
        float acc0 = 0.f, acc1 = 0.f;
#pragma unroll 8
        for (int k = 0; k < WIN_; k++) {
            float wk = __shfl_sync(0xffffffffu, (k < 32) ? w0 : w1, k & 31);
            int row = nl + k;
            acc0 = fmaf(wk, Ks[row][lane],      acc0);
            acc1 = fmaf(wk, Ks[row][lane + 32], acc1);
        }
        // write in [B, N, NH, HD] == [B, N, DIM] layout
        float* orow = attn_out + ((size_t)(b * N_ + n)) * DIM_ + h * HD_;
        orow[lane] = acc0; orow[lane + 32] = acc1;
    }
}

// ------------------------ launch --------------------------------------------
extern "C" void kernel_launch(void* const* d_in, const int* in_sizes, int n_in,
                              void* d_out, int out_size) {
    (void)in_sizes; (void)n_in; (void)out_size;
    const float* x     = (const float*)d_in[0];
    const float* fcos  = (const float*)d_in[1];
    const float* fsin  = (const float*)d_in[2];
    const float* c     = (const float*)d_in[3];
    const float* Wq    = (const float*)d_in[4];
    const float* bq    = (const float*)d_in[5];
    const float* Wk    = (const float*)d_in[6];
    const float* bk    = (const float*)d_in[7];
    const float* Wv    = (const float*)d_in[8];
    const float* bv    = (const float*)d_in[9];
    const float* Wo    = (const float*)d_in[10];
    const float* bo    = (const float*)d_in[11];
    const float* W1    = (const float*)d_in[12];
    const float* b1    = (const float*)d_in[13];
    const float* W2    = (const float*)d_in[14];
    const float* b2    = (const float*)d_in[15];
    const float* ln1s  = (const float*)d_in[16];
    const float* ln1b  = (const float*)d_in[17];
    const float* ln2s  = (const float*)d_in[18];
    const float* ln2b  = (const float*)d_in[19];
    const float* geo   = (const float*)d_in[20];
    const float* hasho = (const float*)d_in[21];
    float* out = (float*)d_out;

    float *xn, *q, *k, *v, *qh, *kh, *vt, *attn, *xout, *hh, *mid;
    cudaGetSymbolAddress((void**)&xn,   g_xn);
    cudaGetSymbolAddress((void**)&q,    g_q);
    cudaGetSymbolAddress((void**)&k,    g_k);
    cudaGetSymbolAddress((void**)&v,    g_v);
    cudaGetSymbolAddress((void**)&qh,   g_qh);
    cudaGetSymbolAddress((void**)&kh,   g_kh);
    cudaGetSymbolAddress((void**)&vt,   g_vt);
    cudaGetSymbolAddress((void**)&attn, g_attn);
    cudaGetSymbolAddress((void**)&xout, g_xout);
    cudaGetSymbolAddress((void**)&hh,   g_h);
    cudaGetSymbolAddress((void**)&mid,  g_mid);

    // 1) LN1
    ln_kernel<<<M_, 128>>>(x, ln1s, ln1b, xn);

    // 2) QKV projections
    dim3 gqkv(DIM_ / BN, M_ / BM);
    gemm_kernel<0><<<gqkv, 256>>>(xn, Wq, bq, nullptr, q, M_, DIM_, DIM_);
    gemm_kernel<0><<<gqkv, 256>>>(xn, Wk, bk, nullptr, k, M_, DIM_, DIM_);
    gemm_kernel<0><<<gqkv, 256>>>(xn, Wv, bv, nullptr, v, M_, DIM_, DIM_);

    // 3) hash + rope + expmap0 + transpose
    prep_kernel<<<M_, 256>>>(q, k, v, fcos, fsin, c, hasho, qh, kh, vt);

    // 4) sliding-window Poincaré attention
    dim3 gattn(N_ / QT, B_ * NH_);
    attn_kernel<<<gattn, 256>>>(qh, kh, vt, c, geo, attn);

    // 5) Wo projection + residual(x) -> x_out
    gemm_kernel<1><<<gqkv, 256>>>(attn, Wo, bo, x, xout, M_, DIM_, DIM_);

    // 6) LN2
    ln_kernel<<<M_, 128>>>(xout, ln2s, ln2b, hh);

    // 7) FFN1 + gelu
    dim3 gffn1(DFF_ / BN, M_ / BM);
    gemm_kernel<2><<<gffn1, 256>>>(hh, W1, b1, nullptr, mid, M_, DFF_, DIM_);

    // 8) FFN2 + residual(x_out) -> out
    gemm_kernel<1><<<gqkv, 256>>>(mid, W2, b2, xout, out, M_, DIM_, DFF_);
}

// round 2
// speedup vs baseline: 1.4133x; 1.4133x over previous
#include <cuda_runtime.h>
#include <cuda_bf16.h>
#include <math.h>

#define B_    2
#define N_    1024
#define DIM_  512
#define NH_   8
#define HD_   64
#define WIN_  64
#define M_    (B_ * N_)      // 2048
#define DFF_  (4 * DIM_)     // 2048
#define EPSV  1e-7f

// ------------------------ scratch (device globals; no allocation) ------------
__device__ float g_xn  [M_ * DIM_];
__device__ float g_q   [M_ * DIM_];
__device__ float g_k   [M_ * DIM_];
__device__ float g_v   [M_ * DIM_];
__device__ float g_qh  [B_ * NH_ * N_ * HD_];
__device__ float g_kh  [B_ * NH_ * N_ * HD_];
__device__ float g_vt  [B_ * NH_ * N_ * HD_];
__device__ float g_attn[M_ * DIM_];
__device__ float g_xout[M_ * DIM_];
__device__ float g_h   [M_ * DIM_];
__device__ float g_mid [M_ * DFF_];

// ------------------------ helpers -------------------------------------------
__device__ __forceinline__ float warpsum(float v) {
#pragma unroll
    for (int o = 16; o > 0; o >>= 1) v += __shfl_xor_sync(0xffffffffu, v, o);
    return v;
}
__device__ __forceinline__ float warpmax(float v) {
#pragma unroll
    for (int o = 16; o > 0; o >>= 1) v = fmaxf(v, __shfl_xor_sync(0xffffffffu, v, o));
    return v;
}
__device__ __forceinline__ float tf32r(float x) {
    asm("cvt.rna.tf32.f32 %0, %1;" : "=f"(x) : "f"(x));
    return x;
}
__device__ __forceinline__ void mma_tf32(float4& c, float a0f, float a1f,
                                         float a2f, float a3f, float b0f, float b1f) {
    unsigned a0 = __float_as_uint(a0f), a1 = __float_as_uint(a1f);
    unsigned a2 = __float_as_uint(a2f), a3 = __float_as_uint(a3f);
    unsigned b0 = __float_as_uint(b0f), b1 = __float_as_uint(b1f);
    asm volatile(
        "mma.sync.aligned.m16n8k8.row.col.f32.tf32.tf32.f32 "
        "{%0,%1,%2,%3},{%4,%5,%6,%7},{%8,%9},{%0,%1,%2,%3};\n"
        : "+f"(c.x), "+f"(c.y), "+f"(c.z), "+f"(c.w)
        : "r"(a0), "r"(a1), "r"(a2), "r"(a3), "r"(b0), "r"(b1));
}

// ------------------------ layernorm -----------------------------------------
__global__ void ln_kernel(const float* __restrict__ x, const float* __restrict__ s,
                          const float* __restrict__ bsh, float* __restrict__ out) {
    int row = blockIdx.x;
    const float* xr = x + (size_t)row * DIM_;
    float v[4];
    float sum = 0.f, sq = 0.f;
#pragma unroll
    for (int i = 0; i < 4; i++) {
        v[i] = xr[threadIdx.x + i * 128];
        sum += v[i];
        sq  += v[i] * v[i];
    }
    __shared__ float red0[4], red1[4];
    sum = warpsum(sum); sq = warpsum(sq);
    int warp = threadIdx.x >> 5, lane = threadIdx.x & 31;
    if (lane == 0) { red0[warp] = sum; red1[warp] = sq; }
    __syncthreads();
    sum = red0[0] + red0[1] + red0[2] + red0[3];
    sq  = red1[0] + red1[1] + red1[2] + red1[3];
    float mean = sum * (1.0f / DIM_);
    float var  = sq * (1.0f / DIM_) - mean * mean;
    float inv  = rsqrtf(var + 1e-6f);
    float* orow = out + (size_t)row * DIM_;
#pragma unroll
    for (int i = 0; i < 4; i++) {
        int d = threadIdx.x + i * 128;
        orow[d] = (v[i] - mean) * inv * s[d] + bsh[d];
    }
}

// ------------------------ tf32 tensor-core GEMM ------------------------------
// C[M,N] = A[M,K] @ B[K,N] (+epilogue). BM=128 BN=64 BK=16, 256 thr (8 warps 4x2)
// warp tile 32x32 = 2(m) x 4(n) mma m16n8k8 tiles, 2 k-steps per BK.
// Smem holds fragments pre-paired: .x = elem(k), .y = elem(k+4), tf32-rounded.
// Strides padded so tig-groups land in disjoint 64B regions mod 256B.
struct GSmem {
    float2 Ap[2][2][4][136];  // [buf][ks][tig][m]  (m stride 136 -> +64B mod 256)
    float2 Bp[2][2][4][72];   // [buf][ks][tig][n]
};

// EPI: 0 = +bias, 1 = +bias+residual, 2 = gelu(+bias)
template <int EPI>
__device__ __forceinline__ void gemm_core(
    const float* __restrict__ A, const float* __restrict__ Bw,
    const float* __restrict__ bias, const float* __restrict__ res,
    float* __restrict__ C, int Nd, int Kd) {
    __shared__ GSmem sm;
    const int m0 = blockIdx.y * 128, n0 = blockIdx.x * 64;
    const int tid = threadIdx.x;
    const int lane = tid & 31, wid = tid >> 5;
    const int g = lane >> 2, tg = lane & 3;     // fragment coords
    const int wm = wid >> 1, wn = wid & 1;      // warp grid 4x2

    // global->smem loader indices
    const int am = tid >> 1, aks = tid & 1;                      // A: 128 rows x 2 k-halves
    const int bks = tid & 1, bn4 = ((tid >> 1) & 15) * 4, btg = tid >> 5;  // B: 16 rows x 16 col-grps
    const float* aPtr = A + (size_t)(m0 + am) * Kd + aks * 8;
    const float* bPtr = Bw + (size_t)(bks * 8 + btg) * Nd + n0 + bn4;
    const int bsel = (btg >> 2) & 1;
    const int bt   = btg & 3;

    float4 acc[2][4];
#pragma unroll
    for (int i = 0; i < 2; i++)
#pragma unroll
        for (int j = 0; j < 4; j++) acc[i][j] = make_float4(0.f, 0.f, 0.f, 0.f);

    // prologue: fetch tile 0
    float4 av0 = *(const float4*)(aPtr);
    float4 av1 = *(const float4*)(aPtr + 4);
    float4 bv  = *(const float4*)(bPtr);

    const int nT = Kd >> 4;
    for (int t = 0; t < nT; t++) {
        const int buf = t & 1;
        // store current tile (tf32-rounded, fragment-paired)
        sm.Ap[buf][aks][0][am] = make_float2(tf32r(av0.x), tf32r(av1.x));
        sm.Ap[buf][aks][1][am] = make_float2(tf32r(av0.y), tf32r(av1.y));
        sm.Ap[buf][aks][2][am] = make_float2(tf32r(av0.z), tf32r(av1.z));
        sm.Ap[buf][aks][3][am] = make_float2(tf32r(av0.w), tf32r(av1.w));
        {
            float* d = (float*)&sm.Bp[buf][bks][bt][bn4];
            d[0 * 2 + bsel] = tf32r(bv.x);
            d[1 * 2 + bsel] = tf32r(bv.y);
            d[2 * 2 + bsel] = tf32r(bv.z);
            d[3 * 2 + bsel] = tf32r(bv.w);
        }
        __syncthreads();
        // prefetch next tile (overlaps compute)
        if (t + 1 < nT) {
            const float* ap = aPtr + (t + 1) * 16;
            av0 = *(const float4*)ap;
            av1 = *(const float4*)(ap + 4);
            bv  = *(const float4*)(bPtr + (size_t)(t + 1) * 16 * Nd);
        }
        // compute
#pragma unroll
        for (int ks = 0; ks < 2; ks++) {
            float2 la[2][2], lb[4];
#pragma unroll
            for (int mi = 0; mi < 2; mi++) {
                la[mi][0] = sm.Ap[buf][ks][tg][wm * 32 + mi * 16 + g];
                la[mi][1] = sm.Ap[buf][ks][tg][wm * 32 + mi * 16 + g + 8];
            }
#pragma unroll
            for (int nj = 0; nj < 4; nj++)
                lb[nj] = sm.Bp[buf][ks][tg][wn * 32 + nj * 8 + g];
#pragma unroll
            for (int mi = 0; mi < 2; mi++)
#pragma unroll
                for (int nj = 0; nj < 4; nj++)
                    mma_tf32(acc[mi][nj],
                             la[mi][0].x, la[mi][1].x, la[mi][0].y, la[mi][1].y,
                             lb[nj].x, lb[nj].y);
        }
        __syncthreads();
    }

    // epilogue: c0/c1 -> (row g, col 2tg/2tg+1), c2/c3 -> row g+8
#pragma unroll
    for (int mi = 0; mi < 2; mi++) {
        int r0 = m0 + wm * 32 + mi * 16 + g;
#pragma unroll
        for (int nj = 0; nj < 4; nj++) {
            int col = n0 + wn * 32 + nj * 8 + tg * 2;
            float2 bb = *(const float2*)(bias + col);
            float4 a = acc[mi][nj];
            float2 o0 = make_float2(a.x + bb.x, a.y + bb.y);
            float2 o1 = make_float2(a.z + bb.x, a.w + bb.y);
            if (EPI == 1) {
                float2 r0v = *(const float2*)(res + (size_t)r0 * Nd + col);
                float2 r1v = *(const float2*)(res + (size_t)(r0 + 8) * Nd + col);
                o0.x += r0v.x; o0.y += r0v.y;
                o1.x += r1v.x; o1.y += r1v.y;
            }
            if (EPI == 2) {
                // gelu(t) = t * sigmoid(1.595769122 * (t + 0.044715 t^3))
                float t0 = o0.x, t1 = o0.y, t2 = o1.x, t3 = o1.y;
                o0.x = t0 / (1.f + __expf(-1.5957691216057308f * (t0 + 0.044715f * t0 * t0 * t0)));
                o0.y = t1 / (1.f + __expf(-1.5957691216057308f * (t1 + 0.044715f * t1 * t1 * t1)));
                o1.x = t2 / (1.f + __expf(-1.5957691216057308f * (t2 + 0.044715f * t2 * t2 * t2)));
                o1.y = t3 / (1.f + __expf(-1.5957691216057308f * (t3 + 0.044715f * t3 * t3 * t3)));
            }
            *(float2*)(C + (size_t)r0 * Nd + col)       = o0;
            *(float2*)(C + (size_t)(r0 + 8) * Nd + col) = o1;
        }
    }
}

// fused QKV: blockIdx.z selects projection (one launch, 384 blocks)
__global__ __launch_bounds__(256, 2) void k_gemm_qkv(
    const float* __restrict__ xn,
    const float* __restrict__ Wq, const float* __restrict__ bq,
    const float* __restrict__ Wk, const float* __restrict__ bk,
    const float* __restrict__ Wv, const float* __restrict__ bv,
    float* __restrict__ q, float* __restrict__ k, float* __restrict__ v) {
    int z = blockIdx.z;
    const float* W  = (z == 0) ? Wq : (z == 1) ? Wk : Wv;
    const float* bb = (z == 0) ? bq : (z == 1) ? bk : bv;
    float* o        = (z == 0) ? q  : (z == 1) ? k  : v;
    gemm_core<0>(xn, W, bb, nullptr, o, DIM_, DIM_);
}

template <int EPI>
__global__ __launch_bounds__(256, 2) void k_gemm(
    const float* __restrict__ A, const float* __restrict__ W,
    const float* __restrict__ bias, const float* __restrict__ res,
    float* __restrict__ C, int Nd, int Kd) {
    gemm_core<EPI>(A, W, bias, res, C, Nd, Kd);
}

// ------------------------ prep: hash + rope + expmap0 + transpose ------------
__global__ void prep_kernel(const float* __restrict__ qb, const float* __restrict__ kb,
                            const float* __restrict__ vb, const float* __restrict__ cos_t,
                            const float* __restrict__ sin_t, const float* __restrict__ c_arr,
                            const float* __restrict__ hash_off,
                            float* __restrict__ qh, float* __restrict__ kh,
                            float* __restrict__ vt) {
    int bn = blockIdx.x;
    int b = bn / N_, n = bn % N_;
    int h = threadIdx.x >> 5, lane = threadIdx.x & 31;
    const float LOG9 = 2.1972245773362196f;  // log(1 + HASH_WIN)
    float cs = cos_t[n * 32 + lane];
    float sn = sin_t[n * 32 + lane];
    float cb = c_arr[b];
    float sqrt_c = fmaxf(sqrtf(cb), EPSV);
    size_t in_off  = (size_t)bn * DIM_ + h * HD_;
    size_t out_off = (((size_t)(b * NH_ + h)) * N_ + n) * HD_;

    {
        float v0 = qb[in_off + lane]      + hash_off[h * HD_ + lane]      * LOG9;
        float v1 = qb[in_off + lane + 32] + hash_off[h * HD_ + lane + 32] * LOG9;
        float r0 = v0 * cs - v1 * sn;
        float r1 = v0 * sn + v1 * cs;
        float nrm = sqrtf(warpsum(r0 * r0 + r1 * r1));
        float o0 = 0.f, o1 = 0.f;
        if (nrm >= EPSV) {
            float safe = fmaxf(nrm, EPSV);
            float mag  = tanhf(sqrt_c * safe) / sqrt_c;
            float sc   = mag / safe;
            o0 = sc * r0; o1 = sc * r1;
        }
        qh[out_off + lane] = o0; qh[out_off + lane + 32] = o1;
    }
    {
        float v0 = kb[in_off + lane];
        float v1 = kb[in_off + lane + 32];
        float r0 = v0 * cs - v1 * sn;
        float r1 = v0 * sn + v1 * cs;
        float nrm = sqrtf(warpsum(r0 * r0 + r1 * r1));
        float o0 = 0.f, o1 = 0.f;
        if (nrm >= EPSV) {
            float safe = fmaxf(nrm, EPSV);
            float mag  = tanhf(sqrt_c * safe) / sqrt_c;
            float sc   = mag / safe;
            o0 = sc * r0; o1 = sc * r1;
        }
        kh[out_off + lane] = o0; kh[out_off + lane + 32] = o1;
    }
    vt[out_off + lane]      = vb[in_off + lane];
    vt[out_off + lane + 32] = vb[in_off + lane + 32];
}

// ------------------------ windowed Poincaré attention ------------------------
#define QT 64
#define KROWS (QT + WIN_ - 1)  // 127
__global__ __launch_bounds__(256) void attn_kernel(
    const float* __restrict__ qh, const float* __restrict__ kh,
    const float* __restrict__ vt, const float* __restrict__ c_arr,
    const float* __restrict__ geo, float* __restrict__ attn_out) {
    __shared__ float Ks[KROWS][HD_];
    __shared__ float y2s[KROWS];
    int bh = blockIdx.y;
    int b = bh / NH_, h = bh % NH_;
    int n0 = blockIdx.x * QT;
    int warp = threadIdx.x >> 5, lane = threadIdx.x & 31;

    const float* Kbase = kh + (size_t)bh * N_ * HD_;
    for (int f = threadIdx.x; f < KROWS * 16; f += 256) {
        int row = f >> 4, c4 = (f & 15) * 4;
        int gn = n0 - (WIN_ - 1) + row;
        float4 val = (gn >= 0) ? *(const float4*)(Kbase + (size_t)gn * HD_ + c4)
                               : make_float4(0.f, 0.f, 0.f, 0.f);
        *(float4*)&Ks[row][c4] = val;
    }
    __syncthreads();
    for (int row = warp; row < KROWS; row += 8) {
        float a = Ks[row][lane], c2 = Ks[row][lane + 32];
        float s = warpsum(a * a + c2 * c2);
        if (lane == 0) y2s[row] = s;
    }
    __syncthreads();

    float cb = c_arr[b];
    float sqrt_c = fmaxf(sqrtf(cb), EPSV);
    float inv_sqrt_c = 1.0f / sqrt_c;
    float gs = geo[h];
    float w0a[8], w1a[8];

    for (int iq = 0; iq < 8; iq++) {
        int nl = warp * 8 + iq;
        int n = n0 + nl;
        const float* qrow = qh + ((size_t)bh * N_ + n) * HD_;
        float q0 = qrow[lane], q1 = qrow[lane + 32];
        float x2 = warpsum(q0 * q0 + q1 * q1);
        float Bc = 1.f - cb * x2;
        float s0 = -1e30f, s1 = -1e30f;
#pragma unroll 4
        for (int k = 0; k < WIN_; k++) {
            int row = nl + k;
            float xy = warpsum(q0 * Ks[row][lane] + q1 * Ks[row][lane + 32]);
            float y2 = y2s[row];
            float A   = 1.f - 2.f * cb * xy + cb * y2;
            float dn2 = A * A * x2 + Bc * Bc * y2 - 2.f * A * Bc * xy;
            float den = fmaxf(1.f - 2.f * cb * xy + cb * cb * x2 * y2, EPSV);
            float dn  = sqrtf(fmaxf(dn2, 0.f)) / den;
            float arg = fminf(sqrt_c * fmaxf(dn, EPSV), 1.f - EPSV);
            float dist = 2.f * atanhf(arg) * inv_sqrt_c;
            float sc = -gs * dist;
            if (k == lane)      s0 = sc;
            if (k == lane + 32) s1 = sc;
        }
        float m  = warpmax(fmaxf(s0, s1));
        float e0 = __expf(s0 - m), e1 = __expf(s1 - m);
        float sum = warpsum(e0 + e1);
        float inv = 1.0f / sum;
        w0a[iq] = e0 * inv; w1a[iq] = e1 * inv;
    }
    __syncthreads();

    const float* Vbase = vt + (size_t)bh * N_ * HD_;
    for (int f = threadIdx.x; f < KROWS * 16; f += 256) {
        int row = f >> 4, c4 = (f & 15) * 4;
        int gn = n0 - (WIN_ - 1) + row;
        float4 val = (gn >= 0) ? *(const float4*)(Vbase + (size_t)gn * HD_ + c4)
                               : make_float4(0.f, 0.f, 0.f, 0.f);
        *(float4*)&Ks[row][c4] = val;
    }
    __syncthreads();

    for (int iq = 0; iq < 8; iq++) {
        int nl = warp * 8 + iq;
        int n = n0 + nl;
        float w0 = w0a[iq], w1 = w1a[iq];
        float acc0 = 0.f, acc1 = 0.f;
#pragma unroll 8
        for (int k = 0; k < WIN_; k++) {
            float wk = __shfl_sync(0xffffffffu, (k < 32) ? w0 : w1, k & 31);
            int row = nl + k;
            acc0 = fmaf(wk, Ks[row][lane],      acc0);
            acc1 = fmaf(wk, Ks[row][lane + 32], acc1);
        }
        float* orow = attn_out + ((size_t)(b * N_ + n)) * DIM_ + h * HD_;
        orow[lane] = acc0; orow[lane + 32] = acc1;
    }
}

// ------------------------ launch --------------------------------------------
extern "C" void kernel_launch(void* const* d_in, const int* in_sizes, int n_in,
                              void* d_out, int out_size) {
    (void)in_sizes; (void)n_in; (void)out_size;
    const float* x     = (const float*)d_in[0];
    const float* fcos  = (const float*)d_in[1];
    const float* fsin  = (const float*)d_in[2];
    const float* c     = (const float*)d_in[3];
    const float* Wq    = (const float*)d_in[4];
    const float* bq    = (const float*)d_in[5];
    const float* Wk    = (const float*)d_in[6];
    const float* bk    = (const float*)d_in[7];
    const float* Wv    = (const float*)d_in[8];
    const float* bv    = (const float*)d_in[9];
    const float* Wo    = (const float*)d_in[10];
    const float* bo    = (const float*)d_in[11];
    const float* W1    = (const float*)d_in[12];
    const float* b1    = (const float*)d_in[13];
    const float* W2    = (const float*)d_in[14];
    const float* b2    = (const float*)d_in[15];
    const float* ln1s  = (const float*)d_in[16];
    const float* ln1b  = (const float*)d_in[17];
    const float* ln2s  = (const float*)d_in[18];
    const float* ln2b  = (const float*)d_in[19];
    const float* geo   = (const float*)d_in[20];
    const float* hasho = (const float*)d_in[21];
    float* out = (float*)d_out;

    float *xn, *q, *k, *v, *qh, *kh, *vt, *attn, *xout, *hh, *mid;
    cudaGetSymbolAddress((void**)&xn,   g_xn);
    cudaGetSymbolAddress((void**)&q,    g_q);
    cudaGetSymbolAddress((void**)&k,    g_k);
    cudaGetSymbolAddress((void**)&v,    g_v);
    cudaGetSymbolAddress((void**)&qh,   g_qh);
    cudaGetSymbolAddress((void**)&kh,   g_kh);
    cudaGetSymbolAddress((void**)&vt,   g_vt);
    cudaGetSymbolAddress((void**)&attn, g_attn);
    cudaGetSymbolAddress((void**)&xout, g_xout);
    cudaGetSymbolAddress((void**)&hh,   g_h);
    cudaGetSymbolAddress((void**)&mid,  g_mid);

    // 1) LN1
    ln_kernel<<<M_, 128>>>(x, ln1s, ln1b, xn);

    // 2) fused QKV projections (one launch, 8x16x3 = 384 blocks)
    dim3 gqkv(DIM_ / 64, M_ / 128, 3);
    k_gemm_qkv<<<gqkv, 256>>>(xn, Wq, bq, Wk, bk, Wv, bv, q, k, v);

    // 3) hash + rope + expmap0 + transpose
    prep_kernel<<<M_, 256>>>(q, k, v, fcos, fsin, c, hasho, qh, kh, vt);

    // 4) sliding-window Poincaré attention
    dim3 gattn(N_ / QT, B_ * NH_);
    attn_kernel<<<gattn, 256>>>(qh, kh, vt, c, geo, attn);

    // 5) Wo projection + residual(x)
    dim3 g512(DIM_ / 64, M_ / 128);
    k_gemm<1><<<g512, 256>>>(attn, Wo, bo, x, xout, DIM_, DIM_);

    // 6) LN2
    ln_kernel<<<M_, 128>>>(xout, ln2s, ln2b, hh);

    // 7) FFN1 + gelu
    dim3 gffn1(DFF_ / 64, M_ / 128);
    k_gemm<2><<<gffn1, 256>>>(hh, W1, b1, nullptr, mid, DFF_, DIM_);

    // 8) FFN2 + residual(x_out) -> out
    k_gemm<1><<<g512, 256>>>(mid, W2, b2, xout, out, DIM_, DFF_);
}

// round 4
// speedup vs baseline: 1.8613x; 1.3170x over previous
#include <cuda_runtime.h>
#include <cuda_bf16.h>
#include <math.h>

#define B_    2
#define N_    1024
#define DIM_  512
#define NH_   8
#define HD_   64
#define WIN_  64
#define M_    (B_ * N_)      // 2048
#define DFF_  (4 * DIM_)     // 2048
#define EPSV  1e-7f

// ------------------------ scratch (device globals; no allocation) ------------
__device__ float g_xn  [M_ * DIM_];
__device__ float g_q   [M_ * DIM_];
__device__ float g_k   [M_ * DIM_];
__device__ float g_v   [M_ * DIM_];
__device__ float g_qh  [B_ * NH_ * N_ * HD_];
__device__ float g_kh  [B_ * NH_ * N_ * HD_];
__device__ float g_vt  [B_ * NH_ * N_ * HD_];
__device__ float g_attn[M_ * DIM_];
__device__ float g_xout[M_ * DIM_];
__device__ float g_h   [M_ * DIM_];
__device__ float g_mid [M_ * DFF_];

// ------------------------ helpers -------------------------------------------
__device__ __forceinline__ float warpsum(float v) {
#pragma unroll
    for (int o = 16; o > 0; o >>= 1) v += __shfl_xor_sync(0xffffffffu, v, o);
    return v;
}
__device__ __forceinline__ float warpmax(float v) {
#pragma unroll
    for (int o = 16; o > 0; o >>= 1) v = fmaxf(v, __shfl_xor_sync(0xffffffffu, v, o));
    return v;
}
__device__ __forceinline__ float tf32r(float x) {
    asm("cvt.rna.tf32.f32 %0, %1;" : "=f"(x) : "f"(x));
    return x;
}
__device__ __forceinline__ float sqrt_fast(float x) {
    float r;
    asm("sqrt.approx.f32 %0, %1;" : "=f"(r) : "f"(x));
    return r;
}
__device__ __forceinline__ void mma_tf32(float4& c, float a0f, float a1f,
                                         float a2f, float a3f, float b0f, float b1f) {
    unsigned a0 = __float_as_uint(a0f), a1 = __float_as_uint(a1f);
    unsigned a2 = __float_as_uint(a2f), a3 = __float_as_uint(a3f);
    unsigned b0 = __float_as_uint(b0f), b1 = __float_as_uint(b1f);
    asm volatile(
        "mma.sync.aligned.m16n8k8.row.col.f32.tf32.tf32.f32 "
        "{%0,%1,%2,%3},{%4,%5,%6,%7},{%8,%9},{%0,%1,%2,%3};\n"
        : "+f"(c.x), "+f"(c.y), "+f"(c.z), "+f"(c.w)
        : "r"(a0), "r"(a1), "r"(a2), "r"(a3), "r"(b0), "r"(b1));
}

// ------------------------ layernorm -----------------------------------------
__global__ void ln_kernel(const float* __restrict__ x, const float* __restrict__ s,
                          const float* __restrict__ bsh, float* __restrict__ out) {
    int row = blockIdx.x;
    const float* xr = x + (size_t)row * DIM_;
    float v[4];
    float sum = 0.f, sq = 0.f;
#pragma unroll
    for (int i = 0; i < 4; i++) {
        v[i] = xr[threadIdx.x + i * 128];
        sum += v[i];
        sq  += v[i] * v[i];
    }
    __shared__ float red0[4], red1[4];
    sum = warpsum(sum); sq = warpsum(sq);
    int warp = threadIdx.x >> 5, lane = threadIdx.x & 31;
    if (lane == 0) { red0[warp] = sum; red1[warp] = sq; }
    __syncthreads();
    sum = red0[0] + red0[1] + red0[2] + red0[3];
    sq  = red1[0] + red1[1] + red1[2] + red1[3];
    float mean = sum * (1.0f / DIM_);
    float var  = sq * (1.0f / DIM_) - mean * mean;
    float inv  = rsqrtf(var + 1e-6f);
    float* orow = out + (size_t)row * DIM_;
#pragma unroll
    for (int i = 0; i < 4; i++) {
        int d = threadIdx.x + i * 128;
        orow[d] = (v[i] - mean) * inv * s[d] + bsh[d];
    }
}

// ------------------------ tf32 tensor-core GEMM ------------------------------
struct GSmem {
    float2 Ap[2][2][4][136];  // [buf][ks][tig][m]
    float2 Bp[2][2][4][72];   // [buf][ks][tig][n]
};

// EPI: 0 = +bias, 1 = +bias+residual, 2 = gelu(+bias)
template <int EPI>
__device__ __forceinline__ void gemm_core(
    const float* __restrict__ A, const float* __restrict__ Bw,
    const float* __restrict__ bias, const float* __restrict__ res,
    float* __restrict__ C, int Nd, int Kd) {
    __shared__ GSmem sm;
    const int m0 = blockIdx.y * 128, n0 = blockIdx.x * 64;
    const int tid = threadIdx.x;
    const int lane = tid & 31, wid = tid >> 5;
    const int g = lane >> 2, tg = lane & 3;
    const int wm = wid >> 1, wn = wid & 1;

    const int am = tid >> 1, aks = tid & 1;
    const int bks = tid & 1, bn4 = ((tid >> 1) & 15) * 4, btg = tid >> 5;
    const float* aPtr = A + (size_t)(m0 + am) * Kd + aks * 8;
    const float* bPtr = Bw + (size_t)(bks * 8 + btg) * Nd + n0 + bn4;
    const int bsel = (btg >> 2) & 1;
    const int bt   = btg & 3;

    float4 acc[2][4];
#pragma unroll
    for (int i = 0; i < 2; i++)
#pragma unroll
        for (int j = 0; j < 4; j++) acc[i][j] = make_float4(0.f, 0.f, 0.f, 0.f);

    float4 av0 = *(const float4*)(aPtr);
    float4 av1 = *(const float4*)(aPtr + 4);
    float4 bv  = *(const float4*)(bPtr);

    const int nT = Kd >> 4;
    for (int t = 0; t < nT; t++) {
        const int buf = t & 1;
        sm.Ap[buf][aks][0][am] = make_float2(tf32r(av0.x), tf32r(av1.x));
        sm.Ap[buf][aks][1][am] = make_float2(tf32r(av0.y), tf32r(av1.y));
        sm.Ap[buf][aks][2][am] = make_float2(tf32r(av0.z), tf32r(av1.z));
        sm.Ap[buf][aks][3][am] = make_float2(tf32r(av0.w), tf32r(av1.w));
        {
            float* d = (float*)&sm.Bp[buf][bks][bt][bn4];
            d[0 * 2 + bsel] = tf32r(bv.x);
            d[1 * 2 + bsel] = tf32r(bv.y);
            d[2 * 2 + bsel] = tf32r(bv.z);
            d[3 * 2 + bsel] = tf32r(bv.w);
        }
        __syncthreads();
        if (t + 1 < nT) {
            const float* ap = aPtr + (t + 1) * 16;
            av0 = *(const float4*)ap;
            av1 = *(const float4*)(ap + 4);
            bv  = *(const float4*)(bPtr + (size_t)(t + 1) * 16 * Nd);
        }
#pragma unroll
        for (int ks = 0; ks < 2; ks++) {
            float2 la[2][2], lb[4];
#pragma unroll
            for (int mi = 0; mi < 2; mi++) {
                la[mi][0] = sm.Ap[buf][ks][tg][wm * 32 + mi * 16 + g];
                la[mi][1] = sm.Ap[buf][ks][tg][wm * 32 + mi * 16 + g + 8];
            }
#pragma unroll
            for (int nj = 0; nj < 4; nj++)
                lb[nj] = sm.Bp[buf][ks][tg][wn * 32 + nj * 8 + g];
#pragma unroll
            for (int mi = 0; mi < 2; mi++)
#pragma unroll
                for (int nj = 0; nj < 4; nj++)
                    mma_tf32(acc[mi][nj],
                             la[mi][0].x, la[mi][1].x, la[mi][0].y, la[mi][1].y,
                             lb[nj].x, lb[nj].y);
        }
        __syncthreads();
    }

#pragma unroll
    for (int mi = 0; mi < 2; mi++) {
        int r0 = m0 + wm * 32 + mi * 16 + g;
#pragma unroll
        for (int nj = 0; nj < 4; nj++) {
            int col = n0 + wn * 32 + nj * 8 + tg * 2;
            float2 bb = *(const float2*)(bias + col);
            float4 a = acc[mi][nj];
            float2 o0 = make_float2(a.x + bb.x, a.y + bb.y);
            float2 o1 = make_float2(a.z + bb.x, a.w + bb.y);
            if (EPI == 1) {
                float2 r0v = *(const float2*)(res + (size_t)r0 * Nd + col);
                float2 r1v = *(const float2*)(res + (size_t)(r0 + 8) * Nd + col);
                o0.x += r0v.x; o0.y += r0v.y;
                o1.x += r1v.x; o1.y += r1v.y;
            }
            if (EPI == 2) {
                float t0 = o0.x, t1 = o0.y, t2 = o1.x, t3 = o1.y;
                o0.x = t0 / (1.f + __expf(-1.5957691216057308f * (t0 + 0.044715f * t0 * t0 * t0)));
                o0.y = t1 / (1.f + __expf(-1.5957691216057308f * (t1 + 0.044715f * t1 * t1 * t1)));
                o1.x = t2 / (1.f + __expf(-1.5957691216057308f * (t2 + 0.044715f * t2 * t2 * t2)));
                o1.y = t3 / (1.f + __expf(-1.5957691216057308f * (t3 + 0.044715f * t3 * t3 * t3)));
            }
            *(float2*)(C + (size_t)r0 * Nd + col)       = o0;
            *(float2*)(C + (size_t)(r0 + 8) * Nd + col) = o1;
        }
    }
}

__global__ __launch_bounds__(256, 2) void k_gemm_qkv(
    const float* __restrict__ xn,
    const float* __restrict__ Wq, const float* __restrict__ bq,
    const float* __restrict__ Wk, const float* __restrict__ bk,
    const float* __restrict__ Wv, const float* __restrict__ bv,
    float* __restrict__ q, float* __restrict__ k, float* __restrict__ v) {
    int z = blockIdx.z;
    const float* W  = (z == 0) ? Wq : (z == 1) ? Wk : Wv;
    const float* bb = (z == 0) ? bq : (z == 1) ? bk : bv;
    float* o        = (z == 0) ? q  : (z == 1) ? k  : v;
    gemm_core<0>(xn, W, bb, nullptr, o, DIM_, DIM_);
}

template <int EPI>
__global__ __launch_bounds__(256, 2) void k_gemm(
    const float* __restrict__ A, const float* __restrict__ W,
    const float* __restrict__ bias, const float* __restrict__ res,
    float* __restrict__ C, int Nd, int Kd) {
    gemm_core<EPI>(A, W, bias, res, C, Nd, Kd);
}

// ------------------------ prep: hash + rope + expmap0 + transpose ------------
__global__ void prep_kernel(const float* __restrict__ qb, const float* __restrict__ kb,
                            const float* __restrict__ vb, const float* __restrict__ cos_t,
                            const float* __restrict__ sin_t, const float* __restrict__ c_arr,
                            const float* __restrict__ hash_off,
                            float* __restrict__ qh, float* __restrict__ kh,
                            float* __restrict__ vt) {
    int bn = blockIdx.x;
    int b = bn / N_, n = bn % N_;
    int h = threadIdx.x >> 5, lane = threadIdx.x & 31;
    const float LOG9 = 2.1972245773362196f;
    float cs = cos_t[n * 32 + lane];
    float sn = sin_t[n * 32 + lane];
    float cb = c_arr[b];
    float sqrt_c = fmaxf(sqrtf(cb), EPSV);
    size_t in_off  = (size_t)bn * DIM_ + h * HD_;
    size_t out_off = (((size_t)(b * NH_ + h)) * N_ + n) * HD_;

    {
        float v0 = qb[in_off + lane]      + hash_off[h * HD_ + lane]      * LOG9;
        float v1 = qb[in_off + lane + 32] + hash_off[h * HD_ + lane + 32] * LOG9;
        float r0 = v0 * cs - v1 * sn;
        float r1 = v0 * sn + v1 * cs;
        float nrm = sqrtf(warpsum(r0 * r0 + r1 * r1));
        float o0 = 0.f, o1 = 0.f;
        if (nrm >= EPSV) {
            float safe = fmaxf(nrm, EPSV);
            float mag  = tanhf(sqrt_c * safe) / sqrt_c;
            float sc   = mag / safe;
            o0 = sc * r0; o1 = sc * r1;
        }
        qh[out_off + lane] = o0; qh[out_off + lane + 32] = o1;
    }
    {
        float v0 = kb[in_off + lane];
        float v1 = kb[in_off + lane + 32];
        float r0 = v0 * cs - v1 * sn;
        float r1 = v0 * sn + v1 * cs;
        float nrm = sqrtf(warpsum(r0 * r0 + r1 * r1));
        float o0 = 0.f, o1 = 0.f;
        if (nrm >= EPSV) {
            float safe = fmaxf(nrm, EPSV);
            float mag  = tanhf(sqrt_c * safe) / sqrt_c;
            float sc   = mag / safe;
            o0 = sc * r0; o1 = sc * r1;
        }
        kh[out_off + lane] = o0; kh[out_off + lane + 32] = o1;
    }
    vt[out_off + lane]      = vb[in_off + lane];
    vt[out_off + lane + 32] = vb[in_off + lane + 32];
}

// ------------------------ windowed Poincaré attention (persistent) -----------
// grid = 152 CTAs x 256 thr; 1024 tiles of QT=16 queries; per tile:
//  K rows [79][stride 65], Q [16][stride 68], scores via per-thread serial dots
//  (thread = 1 query x 4 keys), fused log2-space softmax, V reuses K buffer.
#define QT2    16
#define KR2    (QT2 + WIN_ - 1)   // 79
#define KS_STR 65
#define QS_STR 68
#define SW_STR 65
#define NTILES ((N_ / QT2) * B_ * NH_)   // 1024
#define RMIN_  5.0000003e-8f             // (1e-7)/(2-1e-7)

__global__ __launch_bounds__(256) void attn2_kernel(
    const float* __restrict__ qh, const float* __restrict__ kh,
    const float* __restrict__ vt, const float* __restrict__ c_arr,
    const float* __restrict__ geo, float* __restrict__ attn_out) {
    // __align__(16): these arrays are accessed through float4* casts; a plain
    // __shared__ float[] base is only 4B-aligned -> misaligned-address trap.
    __shared__ __align__(16) float Ks[KR2 * KS_STR + 16];  // K tile; reused for V
    __shared__ __align__(16) float Qs[QT2 * QS_STR];
    __shared__ __align__(16) float Sw[QT2 * SW_STR];
    __shared__ float y2s[KR2 + 1];

    const int tid = threadIdx.x;
    const int w = tid >> 5, l = tid & 31;
    const int qi = tid >> 4;          // 0..15
    const int kg = tid & 15;          // 0..15

    for (int t = blockIdx.x; t < NTILES; t += gridDim.x) {
        const int bh = t >> 6;
        const int b = bh >> 3, h = bh & 7;
        const int n0 = (t & 63) << 4;
        const float* Kb = kh + (size_t)bh * (N_ * HD_);
        const float* Vb = vt + (size_t)bh * (N_ * HD_);
        const float* Qb = qh + (size_t)bh * (N_ * HD_);

        // ---- K tile -> smem (stride 65; scalar stores keep alignment)
#pragma unroll
        for (int i = 0; i < 5; i++) {
            int f = tid + i * 256;
            if (f < KR2 * 16) {
                int row = f >> 4, c4 = (f & 15) << 2;
                int gn = n0 - (WIN_ - 1) + row;
                float4 val = make_float4(0.f, 0.f, 0.f, 0.f);
                if (gn >= 0) val = *(const float4*)(Kb + (size_t)gn * HD_ + c4);
                float* d = &Ks[row * KS_STR + c4];
                d[0] = val.x; d[1] = val.y; d[2] = val.z; d[3] = val.w;
            }
        }
        // ---- Q tile -> smem (stride 68, float4-aligned)
        {
            int row = tid >> 4, c4 = (tid & 15) << 2;
            *(float4*)&Qs[row * QS_STR + c4] =
                *(const float4*)(Qb + (size_t)(n0 + row) * HD_ + c4);
        }
        // ---- prefetch V into registers (latency hidden behind score phase)
        float4 vreg[5];
#pragma unroll
        for (int i = 0; i < 5; i++) {
            int f = tid + i * 256;
            vreg[i] = make_float4(0.f, 0.f, 0.f, 0.f);
            if (f < KR2 * 16) {
                int row = f >> 4, c4 = (f & 15) << 2;
                int gn = n0 - (WIN_ - 1) + row;
                if (gn >= 0) vreg[i] = *(const float4*)(Vb + (size_t)gn * HD_ + c4);
            }
        }
        __syncthreads();

        // ---- y2 per key row
        for (int row = w; row < KR2; row += 8) {
            float a = Ks[row * KS_STR + l];
            float bq = Ks[row * KS_STR + 32 + l];
            float s = warpsum(a * a + bq * bq);
            if (l == 0) y2s[row] = s;
        }
        __syncthreads();

        const float cb = c_arr[b];
        const float sc = fmaxf(sqrtf(cb), EPSV);
        const float gs = geo[h];
        const float p2 = gs / sc;          // w = ratio^(gs/sqrt_c); log2 w = p2*lg2(ratio)
        const float cc = cb * cb;

        // ---- dot products: thread = (query qi, keys kg+16j)
        float xy0 = 0.f, xy1 = 0.f, xy2 = 0.f, xy3 = 0.f, q2 = 0.f;
        {
            const float* qrow = &Qs[qi * QS_STR];
            const float* kr = &Ks[(qi + kg) * KS_STR];
#pragma unroll 8
            for (int d = 0; d < HD_; d++) {
                float qv = qrow[d];
                q2  = fmaf(qv, qv, q2);
                xy0 = fmaf(qv, kr[d], xy0);
                xy1 = fmaf(qv, kr[d + 16 * KS_STR], xy1);
                xy2 = fmaf(qv, kr[d + 32 * KS_STR], xy2);
                xy3 = fmaf(qv, kr[d + 48 * KS_STR], xy3);
            }
        }
        {
            const float Bc = 1.f - cb * q2;
            const float c2x2 = cc * q2;
            float xys[4] = {xy0, xy1, xy2, xy3};
#pragma unroll
            for (int j = 0; j < 4; j++) {
                float xy = xys[j];
                float y2 = y2s[qi + kg + 16 * j];
                float u  = fmaf(-2.f * cb, xy, 1.f);
                float A  = fmaf(cb, y2, u);
                float dn2 = fmaf(A * A, q2, fmaf(Bc * Bc, y2, -2.f * A * Bc * xy));
                float den = fmaxf(fmaf(c2x2, y2, u), EPSV);
                float s   = sc * sqrt_fast(fmaxf(dn2, 0.f));
                float ratio = __fdividef(den - s, den + s);
                ratio = fmaxf(ratio, RMIN_);
                Sw[qi * SW_STR + kg + 16 * j] = p2 * __log2f(ratio);
            }
        }
        __syncthreads();

        // ---- softmax (base-2): warp w handles queries w and w+8
#pragma unroll
        for (int qq = 0; qq < 2; qq++) {
            int q = w + qq * 8;
            float s0 = Sw[q * SW_STR + l];
            float s1 = Sw[q * SW_STR + 32 + l];
            float m = warpmax(fmaxf(s0, s1));
            float e0 = exp2f(s0 - m), e1 = exp2f(s1 - m);
            float inv = __fdividef(1.f, warpsum(e0 + e1));
            Sw[q * SW_STR + l] = e0 * inv;
            Sw[q * SW_STR + 32 + l] = e1 * inv;
        }
        __syncthreads();

        // ---- V regs -> smem (stride 64, float4)
#pragma unroll
        for (int i = 0; i < 5; i++) {
            int f = tid + i * 256;
            if (f < KR2 * 16) {
                int row = f >> 4, c4 = (f & 15) << 2;
                *(float4*)&Ks[row * HD_ + c4] = vreg[i];
            }
        }
        __syncthreads();

        // ---- AV: thread = (query qi, dims dg*4..+3)
        {
            const int dg = tid & 15;
            float4 acc = make_float4(0.f, 0.f, 0.f, 0.f);
            const float* wrow = &Sw[qi * SW_STR];
            const float* vbase = &Ks[qi * HD_ + dg * 4];
#pragma unroll 8
            for (int k = 0; k < WIN_; k++) {
                float wk = wrow[k];
                float4 vv = *(const float4*)(vbase + k * HD_);
                acc.x = fmaf(wk, vv.x, acc.x);
                acc.y = fmaf(wk, vv.y, acc.y);
                acc.z = fmaf(wk, vv.z, acc.z);
                acc.w = fmaf(wk, vv.w, acc.w);
            }
            float* orow = attn_out + ((size_t)(b * N_ + n0 + qi)) * DIM_ + h * HD_ + dg * 4;
            *(float4*)orow = acc;
        }
        __syncthreads();
    }
}

// ------------------------ launch --------------------------------------------
extern "C" void kernel_launch(void* const* d_in, const int* in_sizes, int n_in,
                              void* d_out, int out_size) {
    (void)in_sizes; (void)n_in; (void)out_size;
    const float* x     = (const float*)d_in[0];
    const float* fcos  = (const float*)d_in[1];
    const float* fsin  = (const float*)d_in[2];
    const float* c     = (const float*)d_in[3];
    const float* Wq    = (const float*)d_in[4];
    const float* bq    = (const float*)d_in[5];
    const float* Wk    = (const float*)d_in[6];
    const float* bk    = (const float*)d_in[7];
    const float* Wv    = (const float*)d_in[8];
    const float* bv    = (const float*)d_in[9];
    const float* Wo    = (const float*)d_in[10];
    const float* bo    = (const float*)d_in[11];
    const float* W1    = (const float*)d_in[12];
    const float* b1    = (const float*)d_in[13];
    const float* W2    = (const float*)d_in[14];
    const float* b2    = (const float*)d_in[15];
    const float* ln1s  = (const float*)d_in[16];
    const float* ln1b  = (const float*)d_in[17];
    const float* ln2s  = (const float*)d_in[18];
    const float* ln2b  = (const float*)d_in[19];
    const float* geo   = (const float*)d_in[20];
    const float* hasho = (const float*)d_in[21];
    float* out = (float*)d_out;

    float *xn, *q, *k, *v, *qh, *kh, *vt, *attn, *xout, *hh, *mid;
    cudaGetSymbolAddress((void**)&xn,   g_xn);
    cudaGetSymbolAddress((void**)&q,    g_q);
    cudaGetSymbolAddress((void**)&k,    g_k);
    cudaGetSymbolAddress((void**)&v,    g_v);
    cudaGetSymbolAddress((void**)&qh,   g_qh);
    cudaGetSymbolAddress((void**)&kh,   g_kh);
    cudaGetSymbolAddress((void**)&vt,   g_vt);
    cudaGetSymbolAddress((void**)&attn, g_attn);
    cudaGetSymbolAddress((void**)&xout, g_xout);
    cudaGetSymbolAddress((void**)&hh,   g_h);
    cudaGetSymbolAddress((void**)&mid,  g_mid);

    // 1) LN1
    ln_kernel<<<M_, 128>>>(x, ln1s, ln1b, xn);

    // 2) fused QKV projections
    dim3 gqkv(DIM_ / 64, M_ / 128, 3);
    k_gemm_qkv<<<gqkv, 256>>>(xn, Wq, bq, Wk, bk, Wv, bv, q, k, v);

    // 3) hash + rope + expmap0 + transpose
    prep_kernel<<<M_, 256>>>(q, k, v, fcos, fsin, c, hasho, qh, kh, vt);

    // 4) sliding-window Poincaré attention (persistent, 152 SMs)
    attn2_kernel<<<152, 256>>>(qh, kh, vt, c, geo, attn);

    // 5) Wo projection + residual(x)
    dim3 g512(DIM_ / 64, M_ / 128);
    k_gemm<1><<<g512, 256>>>(attn, Wo, bo, x, xout, DIM_, DIM_);

    // 6) LN2
    ln_kernel<<<M_, 128>>>(xout, ln2s, ln2b, hh);

    // 7) FFN1 + gelu
    dim3 gffn1(DFF_ / 64, M_ / 128);
    k_gemm<2><<<gffn1, 256>>>(hh, W1, b1, nullptr, mid, DFF_, DIM_);

    // 8) FFN2 + residual(x_out) -> out
    k_gemm<1><<<g512, 256>>>(mid, W2, b2, xout, out, DIM_, DFF_);
}